// round 4
// baseline (speedup 1.0000x reference)
#include <cuda_runtime.h>
#include <cstdint>

// VectorQuantizer: encodings [32,64,64,64] f32 (B,D,H,W), codebook [64,512] f32.
// Fused GEMM+argmin+gather. Block = 128 rows x all 512 cw (8 tiles of 64).
// Thread = 4 rows x 8 cw. Accumulators packed over ROW pairs (f32x2); the
// codebook tile is stored pre-duplicated in smem so no per-FMA MOVs are needed.

#define Dv 64
#define Kv 512
#define HW 4096
#define MB 128
#define KT 64
#define NT 8
#define THREADS 256

typedef unsigned long long ull;

__device__ __forceinline__ ull ffma2(ull a, ull b, ull c) {
    ull d; asm("fma.rn.f32x2 %0, %1, %2, %3;" : "=l"(d) : "l"(a), "l"(b), "l"(c)); return d;
}
__device__ __forceinline__ ull fadd2(ull a, ull b) {
    ull d; asm("add.rn.f32x2 %0, %1, %2;" : "=l"(d) : "l"(a), "l"(b)); return d;
}
__device__ __forceinline__ ull fsub2(ull a, ull b) {
    ull d; asm("sub.rn.f32x2 %0, %1, %2;" : "=l"(d) : "l"(a), "l"(b)); return d;
}
__device__ __forceinline__ ull fmul2(ull a, ull b) {
    ull d; asm("mul.rn.f32x2 %0, %1, %2;" : "=l"(d) : "l"(a), "l"(b)); return d;
}
__device__ __forceinline__ ull dup2(float v) {
    ull d; unsigned u = __float_as_uint(v);
    asm("mov.b64 %0, {%1, %1};" : "=l"(d) : "r"(u)); return d;
}
__device__ __forceinline__ void unpack2(ull a, float& l, float& h) {
    unsigned lo, hi; asm("mov.b64 {%0, %1}, %2;" : "=r"(lo), "=r"(hi) : "l"(a));
    l = __uint_as_float(lo); h = __uint_as_float(hi);
}

extern __shared__ float sm[];

__global__ void __launch_bounds__(THREADS, 3)
vq_kernel(const float* __restrict__ enc, const float* __restrict__ cb,
          float* __restrict__ out) {
    float* xs   = sm;                         // [64][128] x tile, d-major
    ull*   cbd  = (ull*)(xs + Dv * MB);       // [64][4][8][2] dup'd cb tile (4096 pairs)
    ull*   eed  = cbd + Dv * KT;              // [512] dup'd codeword norms
    float* xxsh = (float*)(eed + Kv);         // [128] row norms
    int*   bjsh = (int*)(xxsh + MB);          // [128] winning index per row

    const int tid = threadIdx.x;
    const int tr  = tid >> 3;                 // 0..31 : 4-row group
    const int tc  = tid & 7;                  // 0..7  : 8-cw group

    const long long row0 = (long long)blockIdx.x * MB;
    const int b   = (int)(row0 >> 12);
    const int hw0 = (int)(row0 & 4095);
    const float* encb = enc + (long long)b * (Dv * HW) + hw0;

    // ---- stage x tile: xs[d][r] = enc[b][d][hw0+r] (coalesced) ----
    for (int i = tid; i < Dv * MB; i += THREADS) {
        int d = i >> 7, r = i & 127;
        xs[i] = encb[d * HW + r];
    }
    // ---- codeword norms (sequential fmaf over d — validated vs reference), dup'd ----
    for (int j = tid; j < Kv; j += THREADS) {
        float e = 0.0f;
#pragma unroll 8
        for (int d = 0; d < Dv; d++) { float c = cb[d * Kv + j]; e = fmaf(c, c, e); }
        eed[j] = dup2(e);
    }
    __syncthreads();

    // ---- row norms (sequential fmaf over d) ----
    if (tid < MB) {
        float v = 0.0f;
#pragma unroll 8
        for (int d = 0; d < Dv; d++) { float a = xs[d * MB + tid]; v = fmaf(a, a, v); }
        xxsh[tid] = v;
    }

    // ---- stage dup'd cb tile 0 ----
    // layout: pair index = d*64 + (k>>1)*16 + (c>>3)*2 + (k&1), k = c&7
#pragma unroll
    for (int i = 0; i < 16; i++) {
        int idx = i * THREADS + tid;
        int d = idx >> 6, c = idx & 63, k = c & 7;
        float v = cb[d * Kv + c];
        cbd[d * 64 + (k >> 1) * 16 + (c >> 3) * 2 + (k & 1)] = dup2(v);
    }
    __syncthreads();

    // per-thread state: packed row-norm pairs + best tracking for 4 rows
    ull xx2[2];
    xx2[0] = *(const ull*)(xxsh + tr * 4 + 0);
    xx2[1] = *(const ull*)(xxsh + tr * 4 + 2);
    const ull TWO2 = dup2(2.0f);
    float best[4]; int bestj[4];
#pragma unroll
    for (int r = 0; r < 4; r++) { best[r] = 3.4028235e38f; bestj[r] = 0; }

    // ---- main loop over 8 codeword tiles ----
    for (int t = 0; t < NT; t++) {
        ull acc[2][8];
#pragma unroll
        for (int rp = 0; rp < 2; rp++)
#pragma unroll
            for (int k = 0; k < 8; k++) acc[rp][k] = 0ULL;

        const ulonglong2* cb16 = (const ulonglong2*)cbd + tc;   // 16B units

#pragma unroll 2
        for (int d = 0; d < Dv; d++) {
            // 4 rows as 2 packed pairs: one conflict-free LDS.128 broadcast
            ulonglong2 xv = *(const ulonglong2*)(xs + d * MB + tr * 4);
            // 8 dup'd codewords: 4 conflict-free LDS.128 (contiguous 128B stripe)
            ulonglong2 c0 = cb16[d * 32 + 0];
            ulonglong2 c1 = cb16[d * 32 + 8];
            ulonglong2 c2 = cb16[d * 32 + 16];
            ulonglong2 c3 = cb16[d * 32 + 24];
#pragma unroll
            for (int rp = 0; rp < 2; rp++) {
                ull x2 = rp ? xv.y : xv.x;
                acc[rp][0] = ffma2(x2, c0.x, acc[rp][0]);
                acc[rp][1] = ffma2(x2, c0.y, acc[rp][1]);
                acc[rp][2] = ffma2(x2, c1.x, acc[rp][2]);
                acc[rp][3] = ffma2(x2, c1.y, acc[rp][3]);
                acc[rp][4] = ffma2(x2, c2.x, acc[rp][4]);
                acc[rp][5] = ffma2(x2, c2.y, acc[rp][5]);
                acc[rp][6] = ffma2(x2, c3.x, acc[rp][6]);
                acc[rp][7] = ffma2(x2, c3.y, acc[rp][7]);
            }
        }

        // prefetch next tile into registers (overlaps epilogue with L2 latency)
        float pf[16];
        if (t + 1 < NT) {
#pragma unroll
            for (int i = 0; i < 16; i++) {
                int idx = i * THREADS + tid;
                pf[i] = __ldg(&cb[(idx >> 6) * Kv + (t + 1) * KT + (idx & 63)]);
            }
        }

        // epilogue: dist = fl(fl(xx - fl(2*mm)) + ee), strict < , ascending j
        const int jb = t * KT + tc * 8;
#pragma unroll
        for (int k = 0; k < 8; k++) {
            ull ee2 = eed[jb + k];
#pragma unroll
            for (int rp = 0; rp < 2; rp++) {
                ull d2 = fadd2(fsub2(xx2[rp], fmul2(TWO2, acc[rp][k])), ee2);
                float d0, d1; unpack2(d2, d0, d1);
                int r0 = 2 * rp, r1 = 2 * rp + 1;
                if (d0 < best[r0]) { best[r0] = d0; bestj[r0] = jb + k; }
                if (d1 < best[r1]) { best[r1] = d1; bestj[r1] = jb + k; }
            }
        }
        __syncthreads();   // everyone done reading tile t

        if (t + 1 < NT) {
#pragma unroll
            for (int i = 0; i < 16; i++) {
                int idx = i * THREADS + tid;
                int d = idx >> 6, c = idx & 63, k = c & 7;
                cbd[d * 64 + (k >> 1) * 16 + (c >> 3) * 2 + (k & 1)] = dup2(pf[i]);
            }
            __syncthreads();
        }
    }

    // ---- reduce argmin across the 8 tc-lanes of each row group ----
#pragma unroll
    for (int r = 0; r < 4; r++) {
        float bd = best[r];
        int   bj = bestj[r];
#pragma unroll
        for (int off = 1; off < 8; off <<= 1) {
            float od = __shfl_xor_sync(0xffffffffu, bd, off);
            int   oj = __shfl_xor_sync(0xffffffffu, bj, off);
            if (od < bd || (od == bd && oj < bj)) { bd = od; bj = oj; }
        }
        if (tc == 0) bjsh[tr * 4 + r] = bj;
    }
    __syncthreads();

    // ---- gather winning codeword, write [B,D,H,W] coalesced ----
    float* outb = out + (long long)b * (Dv * HW) + hw0;
    const int r  = tid & 127;
    const int d0 = (tid >> 7) * (Dv / 2);
    const int myj = bjsh[r];
#pragma unroll 8
    for (int d = d0; d < d0 + Dv / 2; d++) {
        outb[d * HW + r] = __ldg(&cb[d * Kv + myj]);
    }
}

extern "C" void kernel_launch(void* const* d_in, const int* in_sizes, int n_in,
                              void* d_out, int out_size) {
    const float* enc = (const float*)d_in[0];   // [32,64,64,64]
    const float* cb  = (const float*)d_in[1];   // [64,512]
    float* out = (float*)d_out;

    const int smem_bytes = Dv * MB * 4          // xs       32768
                         + Dv * KT * 8          // cbd      32768
                         + Kv * 8               // eed       4096
                         + MB * 4               // xxsh       512
                         + MB * 4;              // bjsh       512   => 70656
    cudaFuncSetAttribute(vq_kernel, cudaFuncAttributeMaxDynamicSharedMemorySize, smem_bytes);

    const long long n_rows = (long long)out_size / Dv;    // 131072
    const int blocks = (int)(n_rows / MB);                // 1024
    vq_kernel<<<blocks, THREADS, smem_bytes>>>(enc, cb, out);
}

// round 8
// speedup vs baseline: 1.4916x; 1.4916x over previous
#include <cuda_runtime.h>
#include <cuda_bf16.h>
#include <cstdint>

// VectorQuantizer via legacy tensor-core path: mma.sync.m16n8k16 bf16 with a
// 6-term split (x=h1+h2+h3, e=g1+g2+g3 in bf16; products h1g1,h1g2,h2g1,
// h1g3,h2g2,h3g1 accumulated in fp32) == emulated-fp32 GEMM, then fused
// argmin + gather. encodings [32,64,64,64] f32 (B,D,H,W), codebook [64,512] f32.

#define Dv 64
#define Kv 512
#define HW 4096
#define MB 128
#define THREADS 256
#define NCH 64                  // codewords per chunk
#define NCHUNKS (Kv / NCH)      // 8
#define NTL (NCH / 8)           // 8 n-tiles of 8

// ---- smem layout (bytes) ----
#define SA   0                  // 3 x [128 rows][128B] bf16 A splits (swizzled)
#define SB   49152              // 3 x [64 rows][128B]  bf16 B splits (swizzled)
#define SEE  73728              // f32[512]
#define SXX  75776              // f32[128]
#define SBJ  76288              // i32[128]
#define SMTOT 76800

__device__ unsigned g_pack[3][Kv * 32];   // bf16 pairs, [split][j][d2], k-major
__device__ float    g_ee[Kv];

__device__ __forceinline__ void split3(float v, unsigned short& a,
                                       unsigned short& b, unsigned short& c) {
    __nv_bfloat16 h1 = __float2bfloat16_rn(v);
    float r1 = v - __bfloat162float(h1);
    __nv_bfloat16 h2 = __float2bfloat16_rn(r1);
    float r2 = r1 - __bfloat162float(h2);
    __nv_bfloat16 h3 = __float2bfloat16_rn(r2);
    a = __bfloat16_as_ushort(h1);
    b = __bfloat16_as_ushort(h2);
    c = __bfloat16_as_ushort(h3);
}

// ---- kernel 1: split codebook + codeword norms ----
__global__ void __launch_bounds__(512) split_cb_kernel(const float* __restrict__ cb) {
    int j = threadIdx.x;
    float e = 0.0f;
#pragma unroll 4
    for (int d2 = 0; d2 < 32; d2++) {
        float c0 = cb[(2 * d2 + 0) * Kv + j];
        float c1 = cb[(2 * d2 + 1) * Kv + j];
        e = fmaf(c0, c0, e);
        e = fmaf(c1, c1, e);                 // sequential-d: validated ee channel
        unsigned short a0, b0, g0, a1, b1, g1;
        split3(c0, a0, b0, g0);
        split3(c1, a1, b1, g1);
        g_pack[0][j * 32 + d2] = (unsigned)a0 | ((unsigned)a1 << 16);
        g_pack[1][j * 32 + d2] = (unsigned)b0 | ((unsigned)b1 << 16);
        g_pack[2][j * 32 + d2] = (unsigned)g0 | ((unsigned)g1 << 16);
    }
    g_ee[j] = e;
}

#define LDSM_X4(R, addr)                                                     \
    asm volatile("ldmatrix.sync.aligned.m8n8.x4.shared.b16 {%0,%1,%2,%3}, [%4];" \
                 : "=r"((R)[0]), "=r"((R)[1]), "=r"((R)[2]), "=r"((R)[3])    \
                 : "r"(addr))
#define LDSM_X2(R, addr)                                                     \
    asm volatile("ldmatrix.sync.aligned.m8n8.x2.shared.b16 {%0,%1}, [%2];"   \
                 : "=r"((R)[0]), "=r"((R)[1]) : "r"(addr))
#define MMA(C, A, B)                                                         \
    asm volatile("mma.sync.aligned.m16n8k16.row.col.f32.bf16.bf16.f32 "      \
                 "{%0,%1,%2,%3},{%4,%5,%6,%7},{%8,%9},{%0,%1,%2,%3};"        \
                 : "+f"((C)[0]), "+f"((C)[1]), "+f"((C)[2]), "+f"((C)[3])    \
                 : "r"((A)[0]), "r"((A)[1]), "r"((A)[2]), "r"((A)[3]),       \
                   "r"((B)[0]), "r"((B)[1]))

extern __shared__ char smem[];

// ---- kernel 2: fused split-GEMM + argmin + gather ----
__global__ void __launch_bounds__(THREADS, 2)
vq_mma_kernel(const float* __restrict__ enc, const float* __restrict__ cb,
              float* __restrict__ out) {
    unsigned sb;
    asm("{ .reg .u64 t; cvta.to.shared.u64 t, %1; cvt.u32.u64 %0, t; }"
        : "=r"(sb) : "l"(smem));
    const int tid  = threadIdx.x;
    const int wid  = tid >> 5;
    const int lane = tid & 31;

    const long long row0 = (long long)blockIdx.x * MB;
    const int b   = (int)(row0 >> 12);
    const int hw0 = (int)(row0 & 4095);
    const float* encb = enc + (long long)b * (Dv * HW) + hw0;

    float* eesh = (float*)(smem + SEE);
    float* xxsh = (float*)(smem + SXX);
    int*   bjsh = (int*)(smem + SBJ);

    // ---- stage A: split x tile into 3 swizzled bf16 tiles [128][64] ----
    for (int i = tid; i < 32 * MB; i += THREADS) {
        int d2 = i >> 7, m = i & 127;
        float v0 = encb[(2 * d2 + 0) * HW + m];
        float v1 = encb[(2 * d2 + 1) * HW + m];
        unsigned short a0, b0, c0, a1, b1, c1;
        split3(v0, a0, b0, c0);
        split3(v1, a1, b1, c1);
        unsigned off = (unsigned)(m * 128 + (((d2 >> 2) ^ (m & 7)) << 4) + ((d2 & 3) << 2));
        *(unsigned*)(smem + SA +     0 + off) = (unsigned)a0 | ((unsigned)a1 << 16);
        *(unsigned*)(smem + SA + 16384 + off) = (unsigned)b0 | ((unsigned)b1 << 16);
        *(unsigned*)(smem + SA + 32768 + off) = (unsigned)c0 | ((unsigned)c1 << 16);
    }
    eesh[tid]       = g_ee[tid];
    eesh[tid + 256] = g_ee[tid + 256];
    if (tid < MB) {      // row norms, sequential-d fmaf (validated channel)
        float v = 0.0f;
#pragma unroll 8
        for (int d = 0; d < Dv; d++) { float a = encb[d * HW + tid]; v = fmaf(a, a, v); }
        xxsh[tid] = v;
    }

    const int r0 = lane >> 2;         // 0..7 (row within half-stripe)
    const int wr = wid * 16;          // warp row base within block
    float best0 = 3.4028235e38f, best1 = 3.4028235e38f;
    int   bj0 = 0, bj1 = 0;
    float xx0 = 0.0f, xx1 = 0.0f;     // loaded after first sync

    const int rowA   = wr + (lane & 15);      // FIX R7: warp's own 16-row stripe
    const int tA     = lane >> 4;             // 0/1 -> k-chunk select for A
    const int rowBl  = lane & 7;              // within n-tile
    const int tB     = (lane >> 3) & 1;       // k-chunk select for B

    for (int ch = 0; ch < NCHUNKS; ch++) {
        __syncthreads();     // prior chunk's ldmatrix done (and A staging on ch=0)
        // ---- stage B chunk: 3 swizzled bf16 tiles [64][64] ----
        for (int i = tid; i < 3 * NCH * 32; i += THREADS) {
            int s = i >> 11, r = i & 2047;
            int jl = r >> 5, d2 = r & 31;
            unsigned w = g_pack[s][(ch * NCH + jl) * 32 + d2];
            unsigned off = (unsigned)(jl * 128 + (((d2 >> 2) ^ (jl & 7)) << 4) + ((d2 & 3) << 2));
            *(unsigned*)(smem + SB + s * 8192 + off) = w;
        }
        __syncthreads();
        if (ch == 0) { xx0 = xxsh[wr + r0]; xx1 = xxsh[wr + r0 + 8]; }

        float acc[NTL][4];
#pragma unroll
        for (int nt = 0; nt < NTL; nt++)
#pragma unroll
            for (int q = 0; q < 4; q++) acc[nt][q] = 0.0f;

#pragma unroll
        for (int ks = 0; ks < 4; ks++) {
            unsigned a[3][4];
            const unsigned chA = (unsigned)(ks * 2 + tA);
#pragma unroll
            for (int s = 0; s < 3; s++) {
                unsigned addrA = sb + SA + s * 16384 + rowA * 128
                               + (((chA ^ (rowA & 7)) & 7) << 4);
                LDSM_X4(a[s], addrA);
            }
            const unsigned chB = (unsigned)(ks * 2 + tB);
#pragma unroll
            for (int nt = 0; nt < NTL; nt++) {
                unsigned bb[3][2];
                const int rB = nt * 8 + rowBl;
#pragma unroll
                for (int s = 0; s < 3; s++) {
                    unsigned addrB = sb + SB + s * 8192 + rB * 128
                                   + (((chB ^ (rB & 7)) & 7) << 4);
                    LDSM_X2(bb[s], addrB);
                }
                MMA(acc[nt], a[0], bb[0]);   // h1g1
                MMA(acc[nt], a[0], bb[1]);   // h1g2
                MMA(acc[nt], a[1], bb[0]);   // h2g1
                MMA(acc[nt], a[0], bb[2]);   // h1g3
                MMA(acc[nt], a[1], bb[1]);   // h2g2
                MMA(acc[nt], a[2], bb[0]);   // h3g1
            }
        }

        // ---- fold chunk into running argmin (validated dist formula) ----
        const int nb = ch * NCH + (lane & 3) * 2;
#pragma unroll
        for (int nt = 0; nt < NTL; nt++) {
            const int n0 = nb + nt * 8;
            const float e0 = eesh[n0], e1 = eesh[n0 + 1];
            float d00 = __fadd_rn(__fsub_rn(xx0, __fmul_rn(2.0f, acc[nt][0])), e0);
            float d01 = __fadd_rn(__fsub_rn(xx0, __fmul_rn(2.0f, acc[nt][1])), e1);
            float d10 = __fadd_rn(__fsub_rn(xx1, __fmul_rn(2.0f, acc[nt][2])), e0);
            float d11 = __fadd_rn(__fsub_rn(xx1, __fmul_rn(2.0f, acc[nt][3])), e1);
            if (d00 < best0) { best0 = d00; bj0 = n0; }
            if (d01 < best0) { best0 = d01; bj0 = n0 + 1; }
            if (d10 < best1) { best1 = d10; bj1 = n0; }
            if (d11 < best1) { best1 = d11; bj1 = n0 + 1; }
        }
    }

    // ---- reduce argmin within each quad of lanes sharing a row ----
#pragma unroll
    for (int off = 1; off < 4; off <<= 1) {
        float od0 = __shfl_xor_sync(0xffffffffu, best0, off);
        int   oj0 = __shfl_xor_sync(0xffffffffu, bj0,   off);
        float od1 = __shfl_xor_sync(0xffffffffu, best1, off);
        int   oj1 = __shfl_xor_sync(0xffffffffu, bj1,   off);
        if (od0 < best0 || (od0 == best0 && oj0 < bj0)) { best0 = od0; bj0 = oj0; }
        if (od1 < best1 || (od1 == best1 && oj1 < bj1)) { best1 = od1; bj1 = oj1; }
    }
    if ((lane & 3) == 0) {
        bjsh[wr + r0]     = bj0;
        bjsh[wr + r0 + 8] = bj1;
    }
    __syncthreads();

    // ---- gather winning codeword, write [B,D,H,W] coalesced ----
    {
        float* outb = out + (long long)b * (Dv * HW) + hw0;
        const int r  = tid & 127;
        const int d0 = (tid >> 7) * 32;
        const int myj = bjsh[r];
#pragma unroll 8
        for (int d = d0; d < d0 + 32; d++)
            outb[d * HW + r] = __ldg(&cb[d * Kv + myj]);
    }
}

extern "C" void kernel_launch(void* const* d_in, const int* in_sizes, int n_in,
                              void* d_out, int out_size) {
    const float* enc = (const float*)d_in[0];   // [32,64,64,64]
    const float* cb  = (const float*)d_in[1];   // [64,512]
    float* out = (float*)d_out;

    cudaFuncSetAttribute(vq_mma_kernel, cudaFuncAttributeMaxDynamicSharedMemorySize, SMTOT);

    split_cb_kernel<<<1, 512>>>(cb);
    const long long n_rows = (long long)out_size / Dv;    // 131072
    const int blocks = (int)(n_rows / MB);                // 1024
    vq_mma_kernel<<<blocks, THREADS, SMTOT>>>(enc, cb, out);
}

// round 9
// speedup vs baseline: 2.0514x; 1.3753x over previous
#include <cuda_runtime.h>
#include <cuda_bf16.h>
#include <cstdint>

// VectorQuantizer via mma.sync.m16n8k16 bf16 6-term split (emulated fp32 GEMM)
// + fused argmin + gather. R9: cp.async double-buffered B staging, hoisted A
// fragments, B ldmatrix x4 over n-tile pairs.
// encodings [32,64,64,64] f32 (B,D,H,W), codebook [64,512] f32.

#define Dv 64
#define Kv 512
#define HW 4096
#define MB 128
#define THREADS 256
#define NCH 64                  // codewords per chunk
#define NCHUNKS (Kv / NCH)      // 8

// ---- smem layout (bytes) ----
#define SA      0               // 3 x [128 rows][128B] bf16 A splits (swizzled)
#define SBB(p)  (49152 + (p) * 24576)   // 2 x (3 x [64 rows][128B]) B splits
#define SEE     98304           // f32[512]
#define SXX     100352          // f32[128]
#define SBJ     100864          // i32[128]
#define SMTOT   101376

__device__ unsigned g_pack[3][Kv * 32];   // bf16 pairs, [split][j][d2], k-major
__device__ float    g_ee[Kv];

__device__ __forceinline__ void split3(float v, unsigned short& a,
                                       unsigned short& b, unsigned short& c) {
    __nv_bfloat16 h1 = __float2bfloat16_rn(v);
    float r1 = v - __bfloat162float(h1);
    __nv_bfloat16 h2 = __float2bfloat16_rn(r1);
    float r2 = r1 - __bfloat162float(h2);
    __nv_bfloat16 h3 = __float2bfloat16_rn(r2);
    a = __bfloat16_as_ushort(h1);
    b = __bfloat16_as_ushort(h2);
    c = __bfloat16_as_ushort(h3);
}

// ---- kernel 1: split codebook + codeword norms ----
__global__ void __launch_bounds__(512) split_cb_kernel(const float* __restrict__ cb) {
    int j = threadIdx.x;
    float e = 0.0f;
#pragma unroll 4
    for (int d2 = 0; d2 < 32; d2++) {
        float c0 = cb[(2 * d2 + 0) * Kv + j];
        float c1 = cb[(2 * d2 + 1) * Kv + j];
        e = fmaf(c0, c0, e);
        e = fmaf(c1, c1, e);                 // sequential-d: validated ee channel
        unsigned short a0, b0, g0, a1, b1, g1;
        split3(c0, a0, b0, g0);
        split3(c1, a1, b1, g1);
        g_pack[0][j * 32 + d2] = (unsigned)a0 | ((unsigned)a1 << 16);
        g_pack[1][j * 32 + d2] = (unsigned)b0 | ((unsigned)b1 << 16);
        g_pack[2][j * 32 + d2] = (unsigned)g0 | ((unsigned)g1 << 16);
    }
    g_ee[j] = e;
}

#define LDSM_X4(R, addr)                                                     \
    asm volatile("ldmatrix.sync.aligned.m8n8.x4.shared.b16 {%0,%1,%2,%3}, [%4];" \
                 : "=r"((R)[0]), "=r"((R)[1]), "=r"((R)[2]), "=r"((R)[3])    \
                 : "r"(addr))
#define MMA(C, A, B)                                                         \
    asm volatile("mma.sync.aligned.m16n8k16.row.col.f32.bf16.bf16.f32 "      \
                 "{%0,%1,%2,%3},{%4,%5,%6,%7},{%8,%9},{%0,%1,%2,%3};"        \
                 : "+f"((C)[0]), "+f"((C)[1]), "+f"((C)[2]), "+f"((C)[3])    \
                 : "r"((A)[0]), "r"((A)[1]), "r"((A)[2]), "r"((A)[3]),       \
                   "r"((B)[0]), "r"((B)[1]))

__device__ __forceinline__ void cp_async16(unsigned saddr, const void* gptr) {
    unsigned long long g = (unsigned long long)__cvta_generic_to_global((void*)gptr);
    asm volatile("cp.async.cg.shared.global [%0], [%1], 16;" :: "r"(saddr), "l"(g));
}
#define CP_COMMIT() asm volatile("cp.async.commit_group;")
#define CP_WAIT1()  asm volatile("cp.async.wait_group 1;")
#define CP_WAIT0()  asm volatile("cp.async.wait_group 0;")

extern __shared__ char smem[];

// Issue cp.async for one B chunk into buffer p (1536 x 16B; 6 per thread).
__device__ __forceinline__ void stage_b_async(unsigned sb, int ch, int p, int tid) {
#pragma unroll
    for (int it = 0; it < 6; it++) {
        int i = it * THREADS + tid;
        int s = i >> 9, r = i & 511;
        int jl = r >> 3, g = r & 7;
        unsigned dst = sb + SBB(p) + s * 8192 + jl * 128
                     + (((g ^ (jl & 7)) & 7) << 4);
        cp_async16(dst, &g_pack[s][(ch * NCH + jl) * 32 + g * 4]);
    }
    CP_COMMIT();
}

// ---- kernel 2: fused split-GEMM + argmin + gather ----
__global__ void __launch_bounds__(THREADS, 2)
vq_mma_kernel(const float* __restrict__ enc, const float* __restrict__ cb,
              float* __restrict__ out) {
    unsigned sb;
    asm("{ .reg .u64 t; cvta.to.shared.u64 t, %1; cvt.u32.u64 %0, t; }"
        : "=r"(sb) : "l"(smem));
    const int tid  = threadIdx.x;
    const int wid  = tid >> 5;
    const int lane = tid & 31;

    const long long row0 = (long long)blockIdx.x * MB;
    const int b   = (int)(row0 >> 12);
    const int hw0 = (int)(row0 & 4095);
    const float* encb = enc + (long long)b * (Dv * HW) + hw0;

    float* eesh = (float*)(smem + SEE);
    float* xxsh = (float*)(smem + SXX);
    int*   bjsh = (int*)(smem + SBJ);

    // ---- kick off B chunk 0 copy immediately ----
    stage_b_async(sb, 0, 0, tid);

    // ---- stage A: split x tile into 3 swizzled bf16 tiles [128][64] ----
    for (int i = tid; i < 32 * MB; i += THREADS) {
        int d2 = i >> 7, m = i & 127;
        float v0 = encb[(2 * d2 + 0) * HW + m];
        float v1 = encb[(2 * d2 + 1) * HW + m];
        unsigned short a0, b0, c0, a1, b1, c1;
        split3(v0, a0, b0, c0);
        split3(v1, a1, b1, c1);
        unsigned off = (unsigned)(m * 128 + (((d2 >> 2) ^ (m & 7)) << 4) + ((d2 & 3) << 2));
        *(unsigned*)(smem + SA +     0 + off) = (unsigned)a0 | ((unsigned)a1 << 16);
        *(unsigned*)(smem + SA + 16384 + off) = (unsigned)b0 | ((unsigned)b1 << 16);
        *(unsigned*)(smem + SA + 32768 + off) = (unsigned)c0 | ((unsigned)c1 << 16);
    }
    eesh[tid]       = g_ee[tid];
    eesh[tid + 256] = g_ee[tid + 256];
    if (tid < MB) {      // row norms, sequential-d fmaf (validated channel)
        float v = 0.0f;
#pragma unroll 8
        for (int d = 0; d < Dv; d++) { float a = encb[d * HW + tid]; v = fmaf(a, a, v); }
        xxsh[tid] = v;
    }
    __syncthreads();

    const int r0 = lane >> 2;         // 0..7 (row within half-stripe)
    const int wr = wid * 16;          // warp row base within block

    // ---- hoist all A fragments (chunk-invariant): afr[ks][split][4] ----
    const int rowA = wr + (lane & 15);       // warp's own 16-row stripe
    const int tA   = lane >> 4;
    unsigned afr[4][3][4];
#pragma unroll
    for (int ks = 0; ks < 4; ks++) {
        const unsigned chA = (unsigned)(ks * 2 + tA);
#pragma unroll
        for (int s = 0; s < 3; s++) {
            unsigned addrA = sb + SA + s * 16384 + rowA * 128
                           + (((chA ^ (rowA & 7)) & 7) << 4);
            LDSM_X4(afr[ks][s], addrA);
        }
    }
    const float xx0 = xxsh[wr + r0];
    const float xx1 = xxsh[wr + r0 + 8];

    float best0 = 3.4028235e38f, best1 = 3.4028235e38f;
    int   bj0 = 0, bj1 = 0;

    // B x4 lane geometry: lanes 0-15 -> n-tile 2*ntp (k-lo/k-hi), 16-31 -> 2*ntp+1
    const int rBbase = (lane >> 4) * 8 + (lane & 7);
    const int tB     = (lane >> 3) & 1;

    for (int ch = 0; ch < NCHUNKS; ch++) {
        __syncthreads();   // all warps done reading buf (ch+1)&1 from chunk ch-1
        if (ch + 1 < NCHUNKS) {
            stage_b_async(sb, ch + 1, (ch + 1) & 1, tid);
            CP_WAIT1();    // chunk ch's group complete
        } else {
            CP_WAIT0();
        }
        __syncthreads();   // chunk ch data visible to all warps

        const unsigned bbuf = sb + SBB(ch & 1);

        float acc[8][4];
#pragma unroll
        for (int nt = 0; nt < 8; nt++)
#pragma unroll
            for (int q = 0; q < 4; q++) acc[nt][q] = 0.0f;

#pragma unroll
        for (int ks = 0; ks < 4; ks++) {
            const unsigned chB = (unsigned)(ks * 2 + tB);
#pragma unroll
            for (int ntp = 0; ntp < 4; ntp++) {
                const int rB = ntp * 16 + rBbase;
                unsigned bb[3][4];
#pragma unroll
                for (int s = 0; s < 3; s++) {
                    unsigned addrB = bbuf + s * 8192 + rB * 128
                                   + (((chB ^ (rB & 7)) & 7) << 4);
                    LDSM_X4(bb[s], addrB);
                }
#pragma unroll
                for (int u = 0; u < 2; u++) {
                    const int nt = 2 * ntp + u;
                    MMA(acc[nt], afr[ks][0], bb[0] + 2 * u);   // h1g1
                    MMA(acc[nt], afr[ks][0], bb[1] + 2 * u);   // h1g2
                    MMA(acc[nt], afr[ks][1], bb[0] + 2 * u);   // h2g1
                    MMA(acc[nt], afr[ks][0], bb[2] + 2 * u);   // h1g3
                    MMA(acc[nt], afr[ks][1], bb[1] + 2 * u);   // h2g2
                    MMA(acc[nt], afr[ks][2], bb[0] + 2 * u);   // h3g1
                }
            }
        }

        // ---- fold chunk into running argmin (validated dist formula) ----
        const int nb = ch * NCH + (lane & 3) * 2;
#pragma unroll
        for (int nt = 0; nt < 8; nt++) {
            const int n0 = nb + nt * 8;
            const float e0 = eesh[n0], e1 = eesh[n0 + 1];
            float d00 = __fadd_rn(__fsub_rn(xx0, __fmul_rn(2.0f, acc[nt][0])), e0);
            float d01 = __fadd_rn(__fsub_rn(xx0, __fmul_rn(2.0f, acc[nt][1])), e1);
            float d10 = __fadd_rn(__fsub_rn(xx1, __fmul_rn(2.0f, acc[nt][2])), e0);
            float d11 = __fadd_rn(__fsub_rn(xx1, __fmul_rn(2.0f, acc[nt][3])), e1);
            if (d00 < best0) { best0 = d00; bj0 = n0; }
            if (d01 < best0) { best0 = d01; bj0 = n0 + 1; }
            if (d10 < best1) { best1 = d10; bj1 = n0; }
            if (d11 < best1) { best1 = d11; bj1 = n0 + 1; }
        }
    }

    // ---- reduce argmin within each quad of lanes sharing a row ----
#pragma unroll
    for (int off = 1; off < 4; off <<= 1) {
        float od0 = __shfl_xor_sync(0xffffffffu, best0, off);
        int   oj0 = __shfl_xor_sync(0xffffffffu, bj0,   off);
        float od1 = __shfl_xor_sync(0xffffffffu, best1, off);
        int   oj1 = __shfl_xor_sync(0xffffffffu, bj1,   off);
        if (od0 < best0 || (od0 == best0 && oj0 < bj0)) { best0 = od0; bj0 = oj0; }
        if (od1 < best1 || (od1 == best1 && oj1 < bj1)) { best1 = od1; bj1 = oj1; }
    }
    if ((lane & 3) == 0) {
        bjsh[wr + r0]     = bj0;
        bjsh[wr + r0 + 8] = bj1;
    }
    __syncthreads();

    // ---- gather winning codeword, write [B,D,H,W] coalesced ----
    {
        float* outb = out + (long long)b * (Dv * HW) + hw0;
        const int r  = tid & 127;
        const int d0 = (tid >> 7) * 32;
        const int myj = bjsh[r];
#pragma unroll 8
        for (int d = d0; d < d0 + 32; d++)
            outb[d * HW + r] = __ldg(&cb[d * Kv + myj]);
    }
}

extern "C" void kernel_launch(void* const* d_in, const int* in_sizes, int n_in,
                              void* d_out, int out_size) {
    const float* enc = (const float*)d_in[0];   // [32,64,64,64]
    const float* cb  = (const float*)d_in[1];   // [64,512]
    float* out = (float*)d_out;

    cudaFuncSetAttribute(vq_mma_kernel, cudaFuncAttributeMaxDynamicSharedMemorySize, SMTOT);

    split_cb_kernel<<<1, 512>>>(cb);
    const long long n_rows = (long long)out_size / Dv;    // 131072
    const int blocks = (int)(n_rows / MB);                // 1024
    vq_mma_kernel<<<blocks, THREADS, SMTOT>>>(enc, cb, out);
}

// round 10
// speedup vs baseline: 3.0981x; 1.5102x over previous
#include <cuda_runtime.h>
#include <cuda_fp16.h>
#include <cstdint>

// VectorQuantizer via mma.sync.m16n8k16 fp16 3-term split (emulated fp32 GEMM):
// x' = x*2^10 = h1+h2 (fp16), e' = e*2^14 = g1+g2 (fp16);
// mm*2^24 = h1g1 + h1g2 + h2g1 accumulated in fp32 (dropped h2g2 ~ 2^-22 rel).
// Fused argmin + gather. cp.async double-buffered B staging, hoisted A frags.
// encodings [32,64,64,64] f32 (B,D,H,W), codebook [64,512] f32.

#define Dv 64
#define Kv 512
#define HW 4096
#define MB 128
#define THREADS 256
#define NCH 64                  // codewords per chunk
#define NCHUNKS (Kv / NCH)      // 8

#define XSCALE 1024.0f          // 2^10
#define ESCALE 16384.0f         // 2^14
#define INVSC  5.9604644775390625e-8f   // 2^-24, exact

// ---- smem layout (bytes) ----
#define SA      0               // 2 x [128 rows][128B] fp16 A splits (swizzled)
#define SBB(p)  (32768 + (p) * 16384)   // 2 x (2 x [64 rows][128B]) B splits
#define SEE     65536           // f32[512]
#define SXX     67584           // f32[128]
#define SBJ     68096           // i32[128]
#define SMTOT   68608

__device__ unsigned g_pack[2][Kv * 32];   // fp16 pairs, [split][j][d2], k-major
__device__ float    g_ee[Kv];

__device__ __forceinline__ void split2(float v, unsigned short& a, unsigned short& b) {
    __half h1 = __float2half_rn(v);
    float r1 = v - __half2float(h1);
    __half h2 = __float2half_rn(r1);
    a = __half_as_ushort(h1);
    b = __half_as_ushort(h2);
}

// ---- kernel 1: split codebook (scaled) + codeword norms (unscaled) ----
__global__ void __launch_bounds__(512) split_cb_kernel(const float* __restrict__ cb) {
    int j = threadIdx.x;
    float e = 0.0f;
#pragma unroll 4
    for (int d2 = 0; d2 < 32; d2++) {
        float c0 = cb[(2 * d2 + 0) * Kv + j];
        float c1 = cb[(2 * d2 + 1) * Kv + j];
        e = fmaf(c0, c0, e);
        e = fmaf(c1, c1, e);                 // sequential-d: validated ee channel
        unsigned short a0, b0, a1, b1;
        split2(c0 * ESCALE, a0, b0);         // exact power-of-2 scale
        split2(c1 * ESCALE, a1, b1);
        g_pack[0][j * 32 + d2] = (unsigned)a0 | ((unsigned)a1 << 16);
        g_pack[1][j * 32 + d2] = (unsigned)b0 | ((unsigned)b1 << 16);
    }
    g_ee[j] = e;
}

#define LDSM_X4(R, addr)                                                     \
    asm volatile("ldmatrix.sync.aligned.m8n8.x4.shared.b16 {%0,%1,%2,%3}, [%4];" \
                 : "=r"((R)[0]), "=r"((R)[1]), "=r"((R)[2]), "=r"((R)[3])    \
                 : "r"(addr))
#define MMA(C, A, B)                                                         \
    asm volatile("mma.sync.aligned.m16n8k16.row.col.f32.f16.f16.f32 "        \
                 "{%0,%1,%2,%3},{%4,%5,%6,%7},{%8,%9},{%0,%1,%2,%3};"        \
                 : "+f"((C)[0]), "+f"((C)[1]), "+f"((C)[2]), "+f"((C)[3])    \
                 : "r"((A)[0]), "r"((A)[1]), "r"((A)[2]), "r"((A)[3]),       \
                   "r"((B)[0]), "r"((B)[1]))

__device__ __forceinline__ void cp_async16(unsigned saddr, const void* gptr) {
    unsigned long long g = (unsigned long long)__cvta_generic_to_global((void*)gptr);
    asm volatile("cp.async.cg.shared.global [%0], [%1], 16;" :: "r"(saddr), "l"(g));
}
#define CP_COMMIT() asm volatile("cp.async.commit_group;")
#define CP_WAIT1()  asm volatile("cp.async.wait_group 1;")
#define CP_WAIT0()  asm volatile("cp.async.wait_group 0;")

extern __shared__ char smem[];

// Issue cp.async for one B chunk into buffer p (1024 x 16B; 4 per thread).
__device__ __forceinline__ void stage_b_async(unsigned sb, int ch, int p, int tid) {
#pragma unroll
    for (int it = 0; it < 4; it++) {
        int i = it * THREADS + tid;
        int s = i >> 9, r = i & 511;
        int jl = r >> 3, g = r & 7;
        unsigned dst = sb + SBB(p) + s * 8192 + jl * 128
                     + (((g ^ (jl & 7)) & 7) << 4);
        cp_async16(dst, &g_pack[s][(ch * NCH + jl) * 32 + g * 4]);
    }
    CP_COMMIT();
}

// ---- kernel 2: fused split-GEMM + argmin + gather ----
__global__ void __launch_bounds__(THREADS, 2)
vq_mma_kernel(const float* __restrict__ enc, const float* __restrict__ cb,
              float* __restrict__ out) {
    unsigned sb;
    asm("{ .reg .u64 t; cvta.to.shared.u64 t, %1; cvt.u32.u64 %0, t; }"
        : "=r"(sb) : "l"(smem));
    const int tid  = threadIdx.x;
    const int wid  = tid >> 5;
    const int lane = tid & 31;

    const long long row0 = (long long)blockIdx.x * MB;
    const int b   = (int)(row0 >> 12);
    const int hw0 = (int)(row0 & 4095);
    const float* encb = enc + (long long)b * (Dv * HW) + hw0;

    float* eesh = (float*)(smem + SEE);
    float* xxsh = (float*)(smem + SXX);
    int*   bjsh = (int*)(smem + SBJ);

    // ---- kick off B chunk 0 copy immediately ----
    stage_b_async(sb, 0, 0, tid);

    // ---- stage A: split scaled x tile into 2 swizzled fp16 tiles [128][64] ----
    for (int i = tid; i < 32 * MB; i += THREADS) {
        int d2 = i >> 7, m = i & 127;
        float v0 = encb[(2 * d2 + 0) * HW + m] * XSCALE;
        float v1 = encb[(2 * d2 + 1) * HW + m] * XSCALE;
        unsigned short a0, b0, a1, b1;
        split2(v0, a0, b0);
        split2(v1, a1, b1);
        unsigned off = (unsigned)(m * 128 + (((d2 >> 2) ^ (m & 7)) << 4) + ((d2 & 3) << 2));
        *(unsigned*)(smem + SA +     0 + off) = (unsigned)a0 | ((unsigned)a1 << 16);
        *(unsigned*)(smem + SA + 16384 + off) = (unsigned)b0 | ((unsigned)b1 << 16);
    }
    eesh[tid]       = g_ee[tid];
    eesh[tid + 256] = g_ee[tid + 256];
    if (tid < MB) {      // row norms, sequential-d fmaf (validated channel), unscaled
        float v = 0.0f;
#pragma unroll 8
        for (int d = 0; d < Dv; d++) { float a = encb[d * HW + tid]; v = fmaf(a, a, v); }
        xxsh[tid] = v;
    }
    __syncthreads();

    const int r0 = lane >> 2;         // 0..7 (row within half-stripe)
    const int wr = wid * 16;          // warp row base within block

    // ---- hoist all A fragments (chunk-invariant): afr[ks][split][4] ----
    const int rowA = wr + (lane & 15);       // warp's own 16-row stripe
    const int tA   = lane >> 4;
    unsigned afr[4][2][4];
#pragma unroll
    for (int ks = 0; ks < 4; ks++) {
        const unsigned chA = (unsigned)(ks * 2 + tA);
#pragma unroll
        for (int s = 0; s < 2; s++) {
            unsigned addrA = sb + SA + s * 16384 + rowA * 128
                           + (((chA ^ (rowA & 7)) & 7) << 4);
            LDSM_X4(afr[ks][s], addrA);
        }
    }
    const float xx0 = xxsh[wr + r0];
    const float xx1 = xxsh[wr + r0 + 8];

    float best0 = 3.4028235e38f, best1 = 3.4028235e38f;
    int   bj0 = 0, bj1 = 0;

    // B x4 lane geometry: lanes 0-15 -> n-tile 2*ntp, 16-31 -> 2*ntp+1
    const int rBbase = (lane >> 4) * 8 + (lane & 7);
    const int tB     = (lane >> 3) & 1;

    for (int ch = 0; ch < NCHUNKS; ch++) {
        __syncthreads();   // all warps done reading the buffer being overwritten
        if (ch + 1 < NCHUNKS) {
            stage_b_async(sb, ch + 1, (ch + 1) & 1, tid);
            CP_WAIT1();    // chunk ch's group complete
        } else {
            CP_WAIT0();
        }
        __syncthreads();   // chunk ch data visible to all warps

        const unsigned bbuf = sb + SBB(ch & 1);

        float acc[8][4];
#pragma unroll
        for (int nt = 0; nt < 8; nt++)
#pragma unroll
            for (int q = 0; q < 4; q++) acc[nt][q] = 0.0f;

#pragma unroll
        for (int ks = 0; ks < 4; ks++) {
            const unsigned chB = (unsigned)(ks * 2 + tB);
#pragma unroll
            for (int ntp = 0; ntp < 4; ntp++) {
                const int rB = ntp * 16 + rBbase;
                unsigned bb[2][4];
#pragma unroll
                for (int s = 0; s < 2; s++) {
                    unsigned addrB = bbuf + s * 8192 + rB * 128
                                   + (((chB ^ (rB & 7)) & 7) << 4);
                    LDSM_X4(bb[s], addrB);
                }
#pragma unroll
                for (int u = 0; u < 2; u++) {
                    const int nt = 2 * ntp + u;
                    MMA(acc[nt], afr[ks][0], bb[0] + 2 * u);   // h1g1
                    MMA(acc[nt], afr[ks][0], bb[1] + 2 * u);   // h1g2
                    MMA(acc[nt], afr[ks][1], bb[0] + 2 * u);   // h2g1
                }
            }
        }

        // ---- fold chunk into running argmin ----
        // mm = acc * 2^-24 (exact); dist = fl(fl(xx - fl(2*mm)) + ee); strict <
        const int nb = ch * NCH + (lane & 3) * 2;
#pragma unroll
        for (int nt = 0; nt < 8; nt++) {
            const int n0 = nb + nt * 8;
            const float e0 = eesh[n0], e1 = eesh[n0 + 1];
            float m00 = __fmul_rn(acc[nt][0], INVSC);
            float m01 = __fmul_rn(acc[nt][1], INVSC);
            float m10 = __fmul_rn(acc[nt][2], INVSC);
            float m11 = __fmul_rn(acc[nt][3], INVSC);
            float d00 = __fadd_rn(__fsub_rn(xx0, __fmul_rn(2.0f, m00)), e0);
            float d01 = __fadd_rn(__fsub_rn(xx0, __fmul_rn(2.0f, m01)), e1);
            float d10 = __fadd_rn(__fsub_rn(xx1, __fmul_rn(2.0f, m10)), e0);
            float d11 = __fadd_rn(__fsub_rn(xx1, __fmul_rn(2.0f, m11)), e1);
            if (d00 < best0) { best0 = d00; bj0 = n0; }
            if (d01 < best0) { best0 = d01; bj0 = n0 + 1; }
            if (d10 < best1) { best1 = d10; bj1 = n0; }
            if (d11 < best1) { best1 = d11; bj1 = n0 + 1; }
        }
    }

    // ---- reduce argmin within each quad of lanes sharing a row ----
#pragma unroll
    for (int off = 1; off < 4; off <<= 1) {
        float od0 = __shfl_xor_sync(0xffffffffu, best0, off);
        int   oj0 = __shfl_xor_sync(0xffffffffu, bj0,   off);
        float od1 = __shfl_xor_sync(0xffffffffu, best1, off);
        int   oj1 = __shfl_xor_sync(0xffffffffu, bj1,   off);
        if (od0 < best0 || (od0 == best0 && oj0 < bj0)) { best0 = od0; bj0 = oj0; }
        if (od1 < best1 || (od1 == best1 && oj1 < bj1)) { best1 = od1; bj1 = oj1; }
    }
    if ((lane & 3) == 0) {
        bjsh[wr + r0]     = bj0;
        bjsh[wr + r0 + 8] = bj1;
    }
    __syncthreads();

    // ---- gather winning codeword, write [B,D,H,W] coalesced ----
    {
        float* outb = out + (long long)b * (Dv * HW) + hw0;
        const int r  = tid & 127;
        const int d0 = (tid >> 7) * 32;
        const int myj = bjsh[r];
#pragma unroll 8
        for (int d = d0; d < d0 + 32; d++)
            outb[d * HW + r] = __ldg(&cb[d * Kv + myj]);
    }
}

extern "C" void kernel_launch(void* const* d_in, const int* in_sizes, int n_in,
                              void* d_out, int out_size) {
    const float* enc = (const float*)d_in[0];   // [32,64,64,64]
    const float* cb  = (const float*)d_in[1];   // [64,512]
    float* out = (float*)d_out;

    cudaFuncSetAttribute(vq_mma_kernel, cudaFuncAttributeMaxDynamicSharedMemorySize, SMTOT);

    split_cb_kernel<<<1, 512>>>(cb);
    const long long n_rows = (long long)out_size / Dv;    // 131072
    const int blocks = (int)(n_rows / MB);                // 1024
    vq_mma_kernel<<<blocks, THREADS, SMTOT>>>(enc, cb, out);
}